// round 6
// baseline (speedup 1.0000x reference)
#include <cuda_runtime.h>
#include <cuda_fp16.h>

// Problem: GridSamplePScan  B=1, L=16, C=8, H=128, W=128
// out[t,c,h,w] = sum_{k<=t} bilinear(images[k,c], base(h,w) + cum[t]-cum[k])
// x wrapped periodically, zero-padding taps.
//
// R6: precompute cumsum(flows) -> k-loop iterations become fully independent
//     (no serial flow recurrence), unroll x4 so ptxas front-batches gathers
//     and fills the L1tex queue. fp16 NHWC taps kept from R5.

#define L_ 16
#define C_ 8
#define H_ 128
#define W_ 128
#define HW_ (H_ * W_)

// NHWC fp16 images scratch: [L, H, W, C] halves = 4 MB
__device__ __half g_imgT[L_ * H_ * W_ * C_];
// cumulative flows: [L, HW] float2 (x,y) = 2 MB
__device__ float2 g_cum[L_ * HW_];

// ---------------------------------------------------------------------------
// Kernel 1: transpose+quantize images [L,C,H,W] fp32 -> [L,H,W,C] fp16
// ---------------------------------------------------------------------------
__global__ __launch_bounds__(256) void transpose_nhwc_kernel(const float* __restrict__ images) {
    int idx = blockIdx.x * blockDim.x + threadIdx.x;  // over L*H*W
    if (idx >= L_ * HW_) return;
    int k = idx >> 14;           // / (H*W)
    int hw = idx & (HW_ - 1);

    const float* src = images + (size_t)k * C_ * HW_ + hw;
    __half2 h0 = __floats2half2_rn(src[0 * HW_], src[1 * HW_]);
    __half2 h1 = __floats2half2_rn(src[2 * HW_], src[3 * HW_]);
    __half2 h2 = __floats2half2_rn(src[4 * HW_], src[5 * HW_]);
    __half2 h3 = __floats2half2_rn(src[6 * HW_], src[7 * HW_]);

    uint4 pack;
    pack.x = *reinterpret_cast<unsigned int*>(&h0);
    pack.y = *reinterpret_cast<unsigned int*>(&h1);
    pack.z = *reinterpret_cast<unsigned int*>(&h2);
    pack.w = *reinterpret_cast<unsigned int*>(&h3);

    *reinterpret_cast<uint4*>(g_imgT + (size_t)idx * C_) = pack;
}

// ---------------------------------------------------------------------------
// Kernel 2: cumsum of flows over t.  flows layout [L,2,H,W] -> g_cum [L,HW] float2
// ---------------------------------------------------------------------------
__global__ __launch_bounds__(256) void cumsum_flows_kernel(const float* __restrict__ flows) {
    int hw = blockIdx.x * blockDim.x + threadIdx.x;
    if (hw >= HW_) return;
    float ax = 0.0f, ay = 0.0f;
#pragma unroll
    for (int t = 0; t < L_; ++t) {
        ax += flows[(size_t)(t * 2 + 0) * HW_ + hw];
        ay += flows[(size_t)(t * 2 + 1) * HW_ + hw];
        g_cum[t * HW_ + hw] = make_float2(ax, ay);
    }
}

// ---------------------------------------------------------------------------
// Kernel 3: bilinear gather + triangular accumulation.
// One thread per (t, h, w); all 8 channels in registers. fp16 taps, fp32 math.
// All k-iterations independent (rel from precomputed cum) -> deep MLP.
// ---------------------------------------------------------------------------
__device__ __forceinline__ void accum_tap(const uint4 p, const float wgt,
                                          float& a0, float& a1, float& a2, float& a3,
                                          float& a4, float& a5, float& a6, float& a7) {
    __half2 h0 = *reinterpret_cast<const __half2*>(&p.x);
    __half2 h1 = *reinterpret_cast<const __half2*>(&p.y);
    __half2 h2 = *reinterpret_cast<const __half2*>(&p.z);
    __half2 h3 = *reinterpret_cast<const __half2*>(&p.w);
    float2 f0 = __half22float2(h0);
    float2 f1 = __half22float2(h1);
    float2 f2 = __half22float2(h2);
    float2 f3 = __half22float2(h3);
    a0 = fmaf(wgt, f0.x, a0);
    a1 = fmaf(wgt, f0.y, a1);
    a2 = fmaf(wgt, f1.x, a2);
    a3 = fmaf(wgt, f1.y, a3);
    a4 = fmaf(wgt, f2.x, a4);
    a5 = fmaf(wgt, f2.y, a5);
    a6 = fmaf(wgt, f3.x, a6);
    a7 = fmaf(wgt, f3.y, a7);
}

__global__ __launch_bounds__(128) void pscan_sample_kernel(float* __restrict__ out) {
    const int w = threadIdx.x;               // 0..127
    const int h = blockIdx.x;                // 0..127
    const int t = (L_ - 1) - blockIdx.y;     // long blocks (big t) first
    const int hw = h * W_ + w;

    // base grid (pixel centers, normalized, align_corners=False)
    const float bx = (2.0f * (float)w + 1.0f) * (1.0f / (float)W_) - 1.0f;
    const float by = (2.0f * (float)h + 1.0f) * (1.0f / (float)H_) - 1.0f;

    const float2 ct = g_cum[t * HW_ + hw];

    float a0 = 0.f, a1 = 0.f, a2 = 0.f, a3 = 0.f;
    float a4 = 0.f, a5 = 0.f, a6 = 0.f, a7 = 0.f;

#pragma unroll 4
    for (int k = 0; k <= t; ++k) {
        const float2 ck = g_cum[k * HW_ + hw];

        float gx = bx + (ct.x - ck.x);
        float gy = by + (ct.y - ck.y);

        // periodic wrap in x: Python remainder(gx+1, 2) - 1, via floor-mod
        float xp = gx + 1.0f;
        gx = xp - 2.0f * floorf(xp * 0.5f) - 1.0f;

        float ix = (gx + 1.0f) * ((float)W_ * 0.5f) - 0.5f;
        float iy = (gy + 1.0f) * ((float)H_ * 0.5f) - 0.5f;

        float x0f = floorf(ix);
        float y0f = floorf(iy);
        float wx = ix - x0f;
        float wy = iy - y0f;

        int x0 = (int)x0f;
        int y0 = (int)y0f;
        int x1 = x0 + 1;
        int y1 = y0 + 1;

        float vx0 = (x0 >= 0 && x0 < W_) ? 1.0f : 0.0f;
        float vx1 = (x1 >= 0 && x1 < W_) ? 1.0f : 0.0f;
        float vy0 = (y0 >= 0 && y0 < H_) ? 1.0f : 0.0f;
        float vy1 = (y1 >= 0 && y1 < H_) ? 1.0f : 0.0f;

        int cx0 = min(max(x0, 0), W_ - 1);
        int cx1 = min(max(x1, 0), W_ - 1);
        int cy0 = min(max(y0, 0), H_ - 1);
        int cy1 = min(max(y1, 0), H_ - 1);

        float w00 = (1.0f - wx) * (1.0f - wy) * vx0 * vy0;
        float w10 = wx * (1.0f - wy) * vx1 * vy0;
        float w01 = (1.0f - wx) * wy * vx0 * vy1;
        float w11 = wx * wy * vx1 * vy1;

        const __half* imgk = g_imgT + (size_t)k * HW_ * C_;

        uint4 p00 = *reinterpret_cast<const uint4*>(imgk + (size_t)(cy0 * W_ + cx0) * C_);
        uint4 p10 = *reinterpret_cast<const uint4*>(imgk + (size_t)(cy0 * W_ + cx1) * C_);
        uint4 p01 = *reinterpret_cast<const uint4*>(imgk + (size_t)(cy1 * W_ + cx0) * C_);
        uint4 p11 = *reinterpret_cast<const uint4*>(imgk + (size_t)(cy1 * W_ + cx1) * C_);

        accum_tap(p00, w00, a0, a1, a2, a3, a4, a5, a6, a7);
        accum_tap(p10, w10, a0, a1, a2, a3, a4, a5, a6, a7);
        accum_tap(p01, w01, a0, a1, a2, a3, a4, a5, a6, a7);
        accum_tap(p11, w11, a0, a1, a2, a3, a4, a5, a6, a7);
    }

    float* o = out + (size_t)t * C_ * HW_ + hw;
    o[0 * HW_] = a0;
    o[1 * HW_] = a1;
    o[2 * HW_] = a2;
    o[3 * HW_] = a3;
    o[4 * HW_] = a4;
    o[5 * HW_] = a5;
    o[6 * HW_] = a6;
    o[7 * HW_] = a7;
}

// ---------------------------------------------------------------------------
extern "C" void kernel_launch(void* const* d_in, const int* in_sizes, int n_in,
                              void* d_out, int out_size) {
    const float* flows  = (const float*)d_in[0];   // [1,16,2,128,128]
    const float* images = (const float*)d_in[1];   // [1,16,8,128,128]
    float* out = (float*)d_out;                    // [1,16,8,128,128]

    (void)in_sizes; (void)n_in; (void)out_size;

    {
        int total = L_ * HW_;
        transpose_nhwc_kernel<<<(total + 255) / 256, 256>>>(images);
    }
    {
        cumsum_flows_kernel<<<(HW_ + 255) / 256, 256>>>(flows);
    }
    {
        dim3 grid(H_, L_);
        dim3 block(W_);
        pscan_sample_kernel<<<grid, block>>>(out);
    }
}

// round 7
// speedup vs baseline: 1.1617x; 1.1617x over previous
#include <cuda_runtime.h>
#include <cuda_fp16.h>

// Problem: GridSamplePScan  B=1, L=16, C=8, H=128, W=128
// out[t,c,h,w] = sum_{k<=t} bilinear(images[k,c], base(h,w) + cum[t]-cum[k])
// x wrapped periodically, zero-padding taps.
//
// R7: lane-paired gathers. Lanes 2j/2j+1 handle the same sample point's
//     x0/x1 taps, so each gather LDG.128 has lane pairs hitting adjacent 16B
//     (same 128B line ~7/8 of the time): ~18 L1 wavefronts per LDG instead of
//     ~30. Two LDGs per (t,k,pixel) pair (row y0, row y1) -> 2.25 wf/point
//     vs 3.75 before. Final shfl_xor(1) merges the two x-sides.

#define L_ 16
#define C_ 8
#define H_ 128
#define W_ 128
#define HW_ (H_ * W_)

// NHWC fp16 images scratch: [L, H, W, C] halves = 4 MB
__device__ __half g_imgT[L_ * H_ * W_ * C_];
// cumulative flows: [L, HW] float2 (x,y) = 2 MB
__device__ float2 g_cum[L_ * HW_];

// ---------------------------------------------------------------------------
// Kernel 1: transpose+quantize images [L,C,H,W] fp32 -> [L,H,W,C] fp16
// ---------------------------------------------------------------------------
__global__ __launch_bounds__(256) void transpose_nhwc_kernel(const float* __restrict__ images) {
    int idx = blockIdx.x * blockDim.x + threadIdx.x;  // over L*H*W
    if (idx >= L_ * HW_) return;
    int k = idx >> 14;           // / (H*W)
    int hw = idx & (HW_ - 1);

    const float* src = images + (size_t)k * C_ * HW_ + hw;
    __half2 h0 = __floats2half2_rn(src[0 * HW_], src[1 * HW_]);
    __half2 h1 = __floats2half2_rn(src[2 * HW_], src[3 * HW_]);
    __half2 h2 = __floats2half2_rn(src[4 * HW_], src[5 * HW_]);
    __half2 h3 = __floats2half2_rn(src[6 * HW_], src[7 * HW_]);

    uint4 pack;
    pack.x = *reinterpret_cast<unsigned int*>(&h0);
    pack.y = *reinterpret_cast<unsigned int*>(&h1);
    pack.z = *reinterpret_cast<unsigned int*>(&h2);
    pack.w = *reinterpret_cast<unsigned int*>(&h3);

    *reinterpret_cast<uint4*>(g_imgT + (size_t)idx * C_) = pack;
}

// ---------------------------------------------------------------------------
// Kernel 2: cumsum of flows over t.  flows [L,2,H,W] -> g_cum [L,HW] float2
// ---------------------------------------------------------------------------
__global__ __launch_bounds__(256) void cumsum_flows_kernel(const float* __restrict__ flows) {
    int hw = blockIdx.x * blockDim.x + threadIdx.x;
    if (hw >= HW_) return;
    float ax = 0.0f, ay = 0.0f;
#pragma unroll
    for (int t = 0; t < L_; ++t) {
        ax += flows[(size_t)(t * 2 + 0) * HW_ + hw];
        ay += flows[(size_t)(t * 2 + 1) * HW_ + hw];
        g_cum[t * HW_ + hw] = make_float2(ax, ay);
    }
}

// ---------------------------------------------------------------------------
// Kernel 3: bilinear gather + triangular accumulation, lane-paired x-taps.
// Block = 256 threads: thread pair (2j, 2j+1) owns pixel w=j of row h.
// Each lane accumulates its x-side over both y rows; shfl_xor(1) merges.
// ---------------------------------------------------------------------------
__device__ __forceinline__ void accum_tap(const uint4 p, const float wgt,
                                          float& a0, float& a1, float& a2, float& a3,
                                          float& a4, float& a5, float& a6, float& a7) {
    __half2 h0 = *reinterpret_cast<const __half2*>(&p.x);
    __half2 h1 = *reinterpret_cast<const __half2*>(&p.y);
    __half2 h2 = *reinterpret_cast<const __half2*>(&p.z);
    __half2 h3 = *reinterpret_cast<const __half2*>(&p.w);
    float2 f0 = __half22float2(h0);
    float2 f1 = __half22float2(h1);
    float2 f2 = __half22float2(h2);
    float2 f3 = __half22float2(h3);
    a0 = fmaf(wgt, f0.x, a0);
    a1 = fmaf(wgt, f0.y, a1);
    a2 = fmaf(wgt, f1.x, a2);
    a3 = fmaf(wgt, f1.y, a3);
    a4 = fmaf(wgt, f2.x, a4);
    a5 = fmaf(wgt, f2.y, a5);
    a6 = fmaf(wgt, f3.x, a6);
    a7 = fmaf(wgt, f3.y, a7);
}

__global__ __launch_bounds__(256) void pscan_sample_kernel(float* __restrict__ out) {
    const int tid  = threadIdx.x;
    const int w    = tid >> 1;               // pixel column 0..127
    const int side = tid & 1;                // 0 -> x0 tap, 1 -> x1 tap
    const int h = blockIdx.x;                // 0..127
    const int t = (L_ - 1) - blockIdx.y;     // long blocks (big t) first
    const int hw = h * W_ + w;

    // base grid (pixel centers, normalized, align_corners=False)
    const float bx = (2.0f * (float)w + 1.0f) * (1.0f / (float)W_) - 1.0f;
    const float by = (2.0f * (float)h + 1.0f) * (1.0f / (float)H_) - 1.0f;

    const float2 ct = g_cum[t * HW_ + hw];

    float a0 = 0.f, a1 = 0.f, a2 = 0.f, a3 = 0.f;
    float a4 = 0.f, a5 = 0.f, a6 = 0.f, a7 = 0.f;

#pragma unroll 2
    for (int k = 0; k <= t; ++k) {
        const float2 ck = g_cum[k * HW_ + hw];

        float gx = bx + (ct.x - ck.x);
        float gy = by + (ct.y - ck.y);

        // periodic wrap in x: Python remainder(gx+1, 2) - 1, via floor-mod
        float xp = gx + 1.0f;
        gx = xp - 2.0f * floorf(xp * 0.5f) - 1.0f;

        float ix = (gx + 1.0f) * ((float)W_ * 0.5f) - 0.5f;
        float iy = (gy + 1.0f) * ((float)H_ * 0.5f) - 0.5f;

        float x0f = floorf(ix);
        float y0f = floorf(iy);
        float wx = ix - x0f;
        float wy = iy - y0f;

        // this lane's x tap
        int xs = (int)x0f + side;                      // x0 or x1
        float wxs = side ? wx : (1.0f - wx);           // x-side weight
        float vx = (xs >= 0 && xs < W_) ? 1.0f : 0.0f; // zero-pad gate
        int cx = min(max(xs, 0), W_ - 1);

        int y0 = (int)y0f;
        int y1 = y0 + 1;
        float vy0 = (y0 >= 0 && y0 < H_) ? 1.0f : 0.0f;
        float vy1 = (y1 >= 0 && y1 < H_) ? 1.0f : 0.0f;
        int cy0 = min(max(y0, 0), H_ - 1);
        int cy1 = min(max(y1, 0), H_ - 1);

        float wRow0 = wxs * vx * (1.0f - wy) * vy0;
        float wRow1 = wxs * vx * wy * vy1;

        const __half* imgk = g_imgT + (size_t)k * HW_ * C_;

        // two gathers per pair: row y0 and row y1 (lane pairs share lines)
        uint4 p0 = *reinterpret_cast<const uint4*>(imgk + (size_t)(cy0 * W_ + cx) * C_);
        uint4 p1 = *reinterpret_cast<const uint4*>(imgk + (size_t)(cy1 * W_ + cx) * C_);

        accum_tap(p0, wRow0, a0, a1, a2, a3, a4, a5, a6, a7);
        accum_tap(p1, wRow1, a0, a1, a2, a3, a4, a5, a6, a7);
    }

    // merge the two x-sides (lanes 2j and 2j+1)
    a0 += __shfl_xor_sync(0xFFFFFFFFu, a0, 1);
    a1 += __shfl_xor_sync(0xFFFFFFFFu, a1, 1);
    a2 += __shfl_xor_sync(0xFFFFFFFFu, a2, 1);
    a3 += __shfl_xor_sync(0xFFFFFFFFu, a3, 1);
    a4 += __shfl_xor_sync(0xFFFFFFFFu, a4, 1);
    a5 += __shfl_xor_sync(0xFFFFFFFFu, a5, 1);
    a6 += __shfl_xor_sync(0xFFFFFFFFu, a6, 1);
    a7 += __shfl_xor_sync(0xFFFFFFFFu, a7, 1);

    if (side == 0) {
        float* o = out + (size_t)t * C_ * HW_ + hw;
        o[0 * HW_] = a0;
        o[1 * HW_] = a1;
        o[2 * HW_] = a2;
        o[3 * HW_] = a3;
        o[4 * HW_] = a4;
        o[5 * HW_] = a5;
        o[6 * HW_] = a6;
        o[7 * HW_] = a7;
    }
}

// ---------------------------------------------------------------------------
extern "C" void kernel_launch(void* const* d_in, const int* in_sizes, int n_in,
                              void* d_out, int out_size) {
    const float* flows  = (const float*)d_in[0];   // [1,16,2,128,128]
    const float* images = (const float*)d_in[1];   // [1,16,8,128,128]
    float* out = (float*)d_out;                    // [1,16,8,128,128]

    (void)in_sizes; (void)n_in; (void)out_size;

    {
        int total = L_ * HW_;
        transpose_nhwc_kernel<<<(total + 255) / 256, 256>>>(images);
    }
    {
        cumsum_flows_kernel<<<(HW_ + 255) / 256, 256>>>(flows);
    }
    {
        dim3 grid(H_, L_);
        dim3 block(256);
        pscan_sample_kernel<<<grid, block>>>(out);
    }
}

// round 8
// speedup vs baseline: 1.2567x; 1.0817x over previous
#include <cuda_runtime.h>
#include <cuda_fp16.h>

// Problem: GridSamplePScan  B=1, L=16, C=8, H=128, W=128
// out[t,c,h,w] = sum_{k<=t} bilinear(images[k,c], base(h,w) + cum[t]-cum[k])
// x wrapped periodically, zero-padding taps.
//
// R7: lane-paired gathers. Lanes 2j/2j+1 handle the same sample point's
//     x0/x1 taps, so each gather LDG.128 has lane pairs hitting adjacent 16B
//     (same 128B line ~7/8 of the time): ~18 L1 wavefronts per LDG instead of
//     ~30. Two LDGs per (t,k,pixel) pair (row y0, row y1) -> 2.25 wf/point
//     vs 3.75 before. Final shfl_xor(1) merges the two x-sides.

#define L_ 16
#define C_ 8
#define H_ 128
#define W_ 128
#define HW_ (H_ * W_)

// NHWC fp16 images scratch: [L, H, W, C] halves = 4 MB
__device__ __half g_imgT[L_ * H_ * W_ * C_];
// cumulative flows: [L, HW] float2 (x,y) = 2 MB
__device__ float2 g_cum[L_ * HW_];

// ---------------------------------------------------------------------------
// Kernel 1: transpose+quantize images [L,C,H,W] fp32 -> [L,H,W,C] fp16
// ---------------------------------------------------------------------------
__global__ __launch_bounds__(256) void transpose_nhwc_kernel(const float* __restrict__ images) {
    int idx = blockIdx.x * blockDim.x + threadIdx.x;  // over L*H*W
    if (idx >= L_ * HW_) return;
    int k = idx >> 14;           // / (H*W)
    int hw = idx & (HW_ - 1);

    const float* src = images + (size_t)k * C_ * HW_ + hw;
    __half2 h0 = __floats2half2_rn(src[0 * HW_], src[1 * HW_]);
    __half2 h1 = __floats2half2_rn(src[2 * HW_], src[3 * HW_]);
    __half2 h2 = __floats2half2_rn(src[4 * HW_], src[5 * HW_]);
    __half2 h3 = __floats2half2_rn(src[6 * HW_], src[7 * HW_]);

    uint4 pack;
    pack.x = *reinterpret_cast<unsigned int*>(&h0);
    pack.y = *reinterpret_cast<unsigned int*>(&h1);
    pack.z = *reinterpret_cast<unsigned int*>(&h2);
    pack.w = *reinterpret_cast<unsigned int*>(&h3);

    *reinterpret_cast<uint4*>(g_imgT + (size_t)idx * C_) = pack;
}

// ---------------------------------------------------------------------------
// Kernel 2: cumsum of flows over t.  flows [L,2,H,W] -> g_cum [L,HW] float2
// ---------------------------------------------------------------------------
__global__ __launch_bounds__(256) void cumsum_flows_kernel(const float* __restrict__ flows) {
    int hw = blockIdx.x * blockDim.x + threadIdx.x;
    if (hw >= HW_) return;
    float ax = 0.0f, ay = 0.0f;
#pragma unroll
    for (int t = 0; t < L_; ++t) {
        ax += flows[(size_t)(t * 2 + 0) * HW_ + hw];
        ay += flows[(size_t)(t * 2 + 1) * HW_ + hw];
        g_cum[t * HW_ + hw] = make_float2(ax, ay);
    }
}

// ---------------------------------------------------------------------------
// Kernel 3: bilinear gather + triangular accumulation, lane-paired x-taps.
// Block = 256 threads: thread pair (2j, 2j+1) owns pixel w=j of row h.
// Each lane accumulates its x-side over both y rows; shfl_xor(1) merges.
// ---------------------------------------------------------------------------
__device__ __forceinline__ void accum_tap(const uint4 p, const float wgt,
                                          float& a0, float& a1, float& a2, float& a3,
                                          float& a4, float& a5, float& a6, float& a7) {
    __half2 h0 = *reinterpret_cast<const __half2*>(&p.x);
    __half2 h1 = *reinterpret_cast<const __half2*>(&p.y);
    __half2 h2 = *reinterpret_cast<const __half2*>(&p.z);
    __half2 h3 = *reinterpret_cast<const __half2*>(&p.w);
    float2 f0 = __half22float2(h0);
    float2 f1 = __half22float2(h1);
    float2 f2 = __half22float2(h2);
    float2 f3 = __half22float2(h3);
    a0 = fmaf(wgt, f0.x, a0);
    a1 = fmaf(wgt, f0.y, a1);
    a2 = fmaf(wgt, f1.x, a2);
    a3 = fmaf(wgt, f1.y, a3);
    a4 = fmaf(wgt, f2.x, a4);
    a5 = fmaf(wgt, f2.y, a5);
    a6 = fmaf(wgt, f3.x, a6);
    a7 = fmaf(wgt, f3.y, a7);
}

__global__ __launch_bounds__(256) void pscan_sample_kernel(float* __restrict__ out) {
    const int tid  = threadIdx.x;
    const int w    = tid >> 1;               // pixel column 0..127
    const int side = tid & 1;                // 0 -> x0 tap, 1 -> x1 tap
    const int h = blockIdx.x;                // 0..127
    const int t = (L_ - 1) - blockIdx.y;     // long blocks (big t) first
    const int hw = h * W_ + w;

    // base grid (pixel centers, normalized, align_corners=False)
    const float bx = (2.0f * (float)w + 1.0f) * (1.0f / (float)W_) - 1.0f;
    const float by = (2.0f * (float)h + 1.0f) * (1.0f / (float)H_) - 1.0f;

    const float2 ct = g_cum[t * HW_ + hw];

    float a0 = 0.f, a1 = 0.f, a2 = 0.f, a3 = 0.f;
    float a4 = 0.f, a5 = 0.f, a6 = 0.f, a7 = 0.f;

#pragma unroll 2
    for (int k = 0; k <= t; ++k) {
        const float2 ck = g_cum[k * HW_ + hw];

        float gx = bx + (ct.x - ck.x);
        float gy = by + (ct.y - ck.y);

        // periodic wrap in x: Python remainder(gx+1, 2) - 1, via floor-mod
        float xp = gx + 1.0f;
        gx = xp - 2.0f * floorf(xp * 0.5f) - 1.0f;

        float ix = (gx + 1.0f) * ((float)W_ * 0.5f) - 0.5f;
        float iy = (gy + 1.0f) * ((float)H_ * 0.5f) - 0.5f;

        float x0f = floorf(ix);
        float y0f = floorf(iy);
        float wx = ix - x0f;
        float wy = iy - y0f;

        // this lane's x tap
        int xs = (int)x0f + side;                      // x0 or x1
        float wxs = side ? wx : (1.0f - wx);           // x-side weight
        float vx = (xs >= 0 && xs < W_) ? 1.0f : 0.0f; // zero-pad gate
        int cx = min(max(xs, 0), W_ - 1);

        int y0 = (int)y0f;
        int y1 = y0 + 1;
        float vy0 = (y0 >= 0 && y0 < H_) ? 1.0f : 0.0f;
        float vy1 = (y1 >= 0 && y1 < H_) ? 1.0f : 0.0f;
        int cy0 = min(max(y0, 0), H_ - 1);
        int cy1 = min(max(y1, 0), H_ - 1);

        float wRow0 = wxs * vx * (1.0f - wy) * vy0;
        float wRow1 = wxs * vx * wy * vy1;

        const __half* imgk = g_imgT + (size_t)k * HW_ * C_;

        // two gathers per pair: row y0 and row y1 (lane pairs share lines)
        uint4 p0 = *reinterpret_cast<const uint4*>(imgk + (size_t)(cy0 * W_ + cx) * C_);
        uint4 p1 = *reinterpret_cast<const uint4*>(imgk + (size_t)(cy1 * W_ + cx) * C_);

        accum_tap(p0, wRow0, a0, a1, a2, a3, a4, a5, a6, a7);
        accum_tap(p1, wRow1, a0, a1, a2, a3, a4, a5, a6, a7);
    }

    // merge the two x-sides (lanes 2j and 2j+1)
    a0 += __shfl_xor_sync(0xFFFFFFFFu, a0, 1);
    a1 += __shfl_xor_sync(0xFFFFFFFFu, a1, 1);
    a2 += __shfl_xor_sync(0xFFFFFFFFu, a2, 1);
    a3 += __shfl_xor_sync(0xFFFFFFFFu, a3, 1);
    a4 += __shfl_xor_sync(0xFFFFFFFFu, a4, 1);
    a5 += __shfl_xor_sync(0xFFFFFFFFu, a5, 1);
    a6 += __shfl_xor_sync(0xFFFFFFFFu, a6, 1);
    a7 += __shfl_xor_sync(0xFFFFFFFFu, a7, 1);

    if (side == 0) {
        float* o = out + (size_t)t * C_ * HW_ + hw;
        o[0 * HW_] = a0;
        o[1 * HW_] = a1;
        o[2 * HW_] = a2;
        o[3 * HW_] = a3;
        o[4 * HW_] = a4;
        o[5 * HW_] = a5;
        o[6 * HW_] = a6;
        o[7 * HW_] = a7;
    }
}

// ---------------------------------------------------------------------------
extern "C" void kernel_launch(void* const* d_in, const int* in_sizes, int n_in,
                              void* d_out, int out_size) {
    const float* flows  = (const float*)d_in[0];   // [1,16,2,128,128]
    const float* images = (const float*)d_in[1];   // [1,16,8,128,128]
    float* out = (float*)d_out;                    // [1,16,8,128,128]

    (void)in_sizes; (void)n_in; (void)out_size;

    {
        int total = L_ * HW_;
        transpose_nhwc_kernel<<<(total + 255) / 256, 256>>>(images);
    }
    {
        cumsum_flows_kernel<<<(HW_ + 255) / 256, 256>>>(flows);
    }
    {
        dim3 grid(H_, L_);
        dim3 block(256);
        pscan_sample_kernel<<<grid, block>>>(out);
    }
}